// round 13
// baseline (speedup 1.0000x reference)
#include <cuda_runtime.h>

// weight: [2304, 1280] fp32 (G=48); grid_thw = [[2,64,64]]*8
// output: 65536 x 1280 fp32 (335.5 MB) — DRAM-write-bound (write wall
// measured at ~6.55 TB/s steady state for the STG.cs path; R10/R11 51.3us).
//
// Output row = k*4096 + hb*128 + wb*4 + (hm*2+wm), k = 2e+t in [0,16).
// R13 (= R12 theory, build-fixed): TMA bulk-store path instead of STG.
// One CTA per (hb,wb) patch computes its 4 consecutive output rows
// (20 KB) into SMEM once, then issues 16 cp.async.bulk S2G stores
// (one 20 KB contiguous burst per k-replica) with an L2::evict_first
// cache policy so the 11.8 MB weight table stays L2-resident across
// graph replays (the proven .cs win, ported to the TMA path).

#define G_    48
#define D_    1280
#define V4_   320              // float4 per row
#define REPS  16
#define PATCH_BYTES (4 * D_ * 4)       // 4 rows * 5120 B = 20480 B
#define ROWSTRIDE_F (4096 * D_)        // float stride between k-replicas

typedef unsigned long long u64;
typedef unsigned int u32;

__global__ __launch_bounds__(640)
void pe_patch_tma_kernel(const float* __restrict__ W, float* __restrict__ out)
{
    __shared__ __align__(128) float rows[4 * D_];   // 4 sub-rows, output order

    const int pid = blockIdx.x;          // 0..1023
    const int hb  = pid >> 5;            // 0..31
    const int wb  = pid & 31;            // 0..31

    const int tid = threadIdx.x;         // 0..639
    const int s   = (tid >= V4_) ? 1 : 0;
    const int c   = tid - s * V4_;       // float4 column 0..319

    // Each thread computes sub-rows m = s and m = s+2 (m = hm*2 + wm)
    #pragma unroll
    for (int j = 0; j < 2; ++j) {
        const int m  = s + 2 * j;
        const int hm = m >> 1;
        const int wm = m & 1;
        const int h  = 2 * hb + hm;
        const int w  = 2 * wb + wm;

        // linspace(0,47,64): v = i*47/63; integer numerator -> exact floor
        const float vh = (float)(h * (G_ - 1)) * (1.0f / 63.0f);
        const float vw = (float)(w * (G_ - 1)) * (1.0f / 63.0f);
        const int hf = (int)vh;
        const int wf = (int)vw;
        const int hc = min(hf + 1, G_ - 1);
        const int wc = min(wf + 1, G_ - 1);
        const float dh = vh - (float)hf;
        const float dw = vw - (float)wf;

        const float c00 = (1.0f - dh) * (1.0f - dw);
        const float c01 = (1.0f - dh) * dw;
        const float c10 = dh * (1.0f - dw);
        const float c11 = dh * dw;

        const float4 a = *(const float4*)(W + (size_t)(hf * G_ + wf) * D_ + 4 * c);
        const float4 b = *(const float4*)(W + (size_t)(hf * G_ + wc) * D_ + 4 * c);
        const float4 p = *(const float4*)(W + (size_t)(hc * G_ + wf) * D_ + 4 * c);
        const float4 q = *(const float4*)(W + (size_t)(hc * G_ + wc) * D_ + 4 * c);

        float4 v;
        v.x = c00 * a.x + c01 * b.x + c10 * p.x + c11 * q.x;
        v.y = c00 * a.y + c01 * b.y + c10 * p.y + c11 * q.y;
        v.z = c00 * a.z + c01 * b.z + c10 * p.z + c11 * q.z;
        v.w = c00 * a.w + c01 * b.w + c10 * p.w + c11 * q.w;

        ((float4*)rows)[m * V4_ + c] = v;
    }

    __syncthreads();

    if (tid == 0) {
        // make generic-proxy SMEM writes visible to the async (TMA) proxy
        asm volatile("fence.proxy.async.shared::cta;" ::: "memory");

        u64 pol;
        asm("createpolicy.fractional.L2::evict_first.b64 %0, 1.0;" : "=l"(pol));

        u32 saddr;
        asm("{ .reg .u64 t; cvta.to.shared.u64 t, %1; cvt.u32.u64 %0, t; }"
            : "=r"(saddr) : "l"(rows));

        const int rb = hb * 128 + wb * 4;        // base output row of patch
        const float* dst0 = out + (size_t)rb * D_;

        #pragma unroll
        for (int k = 0; k < REPS; ++k) {
            const float* dst = dst0 + (size_t)k * ROWSTRIDE_F;
            asm volatile(
                "cp.async.bulk.global.shared::cta.bulk_group.L2::cache_hint"
                " [%0], [%1], %2, %3;"
                :: "l"(dst), "r"(saddr), "n"(PATCH_BYTES), "l"(pol)
                : "memory");
        }
        asm volatile("cp.async.bulk.commit_group;" ::: "memory");
        // SMEM must stay alive until TMA has read it
        asm volatile("cp.async.bulk.wait_group.read 0;" ::: "memory");
    }
}

extern "C" void kernel_launch(void* const* d_in, const int* in_sizes, int n_in,
                              void* d_out, int out_size)
{
    const float* weight = (const float*)d_in[0];
    (void)in_sizes; (void)n_in; (void)out_size;
    pe_patch_tma_kernel<<<1024, 640>>>(weight, (float*)d_out);
}

// round 14
// speedup vs baseline: 1.0385x; 1.0385x over previous
#include <cuda_runtime.h>

// weight: [2304, 1280] fp32 (G=48); grid_thw = [[2,64,64]]*8
// output: 65536 x 1280 fp32 (335.5 MB) — DRAM-write-bound.
//
// Output row = k*4096 + hb*128 + wb*4 + (hm*2+wm), k = 2e+t in [0,16).
// Champion (R11, 51.26us): one thread per (distinct row, float4 col),
// 5120 CTAs x 256 thr (100% occ), 16 k-replica streaming stores; steady
// state = 6.54 TB/s pure writes (~82% of spec).
//
// R14 single change: __stcs -> __stwt (st.global.wt). Write-through sends
// stores toward DRAM in ISSUE order without allocating dirty L2 lines:
// tests the in-order-burst theory cleanly (R13's TMA test was confounded
// by an occupancy collapse), and maximally protects the L2-resident
// weight table. Same store set, bitwise-identical output.

#define G_   48
#define D_   1280
#define V4_  320         // float4 per row
#define REPS 16
#define ROWSTRIDE4 (4096 * V4_)
#define NTHREADS (4096 * V4_)

__global__ __launch_bounds__(256)
void pe_interp_wt_kernel(const float* __restrict__ W, float* __restrict__ out)
{
    const int gid = blockIdx.x * 256 + threadIdx.x;   // 0 .. 4096*320-1
    const int hw  = gid / V4_;        // distinct row 0..4095
    const int c   = gid - hw * V4_;   // float4 column 0..319

    const int h = hw >> 6;            // 0..63
    const int w = hw & 63;

    // linspace(0,47,64): v = i*47/63; integer numerator -> exact floor
    const float vh = (float)(h * (G_ - 1)) * (1.0f / 63.0f);
    const float vw = (float)(w * (G_ - 1)) * (1.0f / 63.0f);
    const int hf = (int)vh;
    const int wf = (int)vw;
    const int hc = min(hf + 1, G_ - 1);
    const int wc = min(wf + 1, G_ - 1);
    const float dh = vh - (float)hf;
    const float dw = vw - (float)wf;

    const float c00 = (1.0f - dh) * (1.0f - dw);
    const float c01 = (1.0f - dh) * dw;
    const float c10 = dh * (1.0f - dw);
    const float c11 = dh * dw;

    const float4 a = *(const float4*)(W + (size_t)(hf * G_ + wf) * D_ + 4 * c);
    const float4 b = *(const float4*)(W + (size_t)(hf * G_ + wc) * D_ + 4 * c);
    const float4 p = *(const float4*)(W + (size_t)(hc * G_ + wf) * D_ + 4 * c);
    const float4 q = *(const float4*)(W + (size_t)(hc * G_ + wc) * D_ + 4 * c);

    float4 v;
    v.x = c00 * a.x + c01 * b.x + c10 * p.x + c11 * q.x;
    v.y = c00 * a.y + c01 * b.y + c10 * p.y + c11 * q.y;
    v.z = c00 * a.z + c01 * b.z + c10 * p.z + c11 * q.z;
    v.w = c00 * a.w + c01 * b.w + c10 * p.w + c11 * q.w;

    // destination row within one k-block of 4096 rows
    const int hb = h >> 1, hm = h & 1;
    const int wb = w >> 1, wm = w & 1;
    const int rloc = hb * 128 + wb * 4 + hm * 2 + wm;

    float4* __restrict__ o = (float4*)out;
    const size_t base = (size_t)rloc * V4_ + c;

    #pragma unroll
    for (int k = 0; k < REPS; ++k)
        __stwt(o + base + (size_t)k * ROWSTRIDE4, v);   // write-through stores

}

extern "C" void kernel_launch(void* const* d_in, const int* in_sizes, int n_in,
                              void* d_out, int out_size)
{
    const float* weight = (const float*)d_in[0];
    (void)in_sizes; (void)n_in; (void)out_size;
    pe_interp_wt_kernel<<<NTHREADS / 256, 256>>>(weight, (float*)d_out);
}

// round 15
// speedup vs baseline: 1.1597x; 1.1167x over previous
#include <cuda_runtime.h>

// FINAL (champion, R11): bilinear pos-embed interpolation + spatial-merge.
// weight: [2304, 1280] fp32 (G=48); grid_thw = [[2,64,64]]*8
// output: 65536 x 1280 fp32 (335.5 MB) — DRAM-write-bound.
//
// Output row = k*4096 + hb*128 + wb*4 + (hm*2+wm), k = 2e+t in [0,16):
// each of the 4096 distinct interpolated rows is computed once and stored
// 16x at stride 4096 rows.
//
// Tuning verdicts from R1-R14:
//  - __stcs streaming stores: ~4us steady-state win (L2 write-coalescing +
//    keeps the 11.8 MB weight table L2-resident across graph replays).
//    .wt (R14) and TMA bulk (R13) and L2 pinning (R7) all lose.
//  - DRAM busy rises with resident CTA count, saturating near ~888 CTAs;
//    this config (5120 CTAs x 256 thr, 8 CTAs/SM, 100% occ) sits at the
//    saturation point. Persistent grid (R9) and fat v8 stores (R4) lose.
//  - Steady state = 6.54 TB/s pure writes (~82% of 8 TB/s spec) = the
//    HBM3e write-turnaround wall; three independent attempts to exceed it
//    (burst ordering, pinning, path change) all falsified.

#define G_   48
#define D_   1280
#define V4_  320         // float4 per row
#define REPS 16
#define ROWSTRIDE4 (4096 * V4_)
#define NTHREADS (4096 * V4_)

__global__ __launch_bounds__(256)
void pe_interp_flat_kernel(const float* __restrict__ W, float* __restrict__ out)
{
    const int gid = blockIdx.x * 256 + threadIdx.x;   // 0 .. 4096*320-1
    const int hw  = gid / V4_;        // distinct row 0..4095
    const int c   = gid - hw * V4_;   // float4 column 0..319

    const int h = hw >> 6;            // 0..63
    const int w = hw & 63;

    // linspace(0,47,64): v = i*47/63; integer numerator -> exact floor
    const float vh = (float)(h * (G_ - 1)) * (1.0f / 63.0f);
    const float vw = (float)(w * (G_ - 1)) * (1.0f / 63.0f);
    const int hf = (int)vh;
    const int wf = (int)vw;
    const int hc = min(hf + 1, G_ - 1);
    const int wc = min(wf + 1, G_ - 1);
    const float dh = vh - (float)hf;
    const float dw = vw - (float)wf;

    const float c00 = (1.0f - dh) * (1.0f - dw);
    const float c01 = (1.0f - dh) * dw;
    const float c10 = dh * (1.0f - dw);
    const float c11 = dh * dw;

    const float4 a = *(const float4*)(W + (size_t)(hf * G_ + wf) * D_ + 4 * c);
    const float4 b = *(const float4*)(W + (size_t)(hf * G_ + wc) * D_ + 4 * c);
    const float4 p = *(const float4*)(W + (size_t)(hc * G_ + wf) * D_ + 4 * c);
    const float4 q = *(const float4*)(W + (size_t)(hc * G_ + wc) * D_ + 4 * c);

    float4 v;
    v.x = c00 * a.x + c01 * b.x + c10 * p.x + c11 * q.x;
    v.y = c00 * a.y + c01 * b.y + c10 * p.y + c11 * q.y;
    v.z = c00 * a.z + c01 * b.z + c10 * p.z + c11 * q.z;
    v.w = c00 * a.w + c01 * b.w + c10 * p.w + c11 * q.w;

    // destination row within one k-block of 4096 rows
    const int hb = h >> 1, hm = h & 1;
    const int wb = w >> 1, wm = w & 1;
    const int rloc = hb * 128 + wb * 4 + hm * 2 + wm;

    float4* __restrict__ o = (float4*)out;
    const size_t base = (size_t)rloc * V4_ + c;

    #pragma unroll
    for (int k = 0; k < REPS; ++k)
        __stcs(o + base + (size_t)k * ROWSTRIDE4, v);   // streaming stores
}

extern "C" void kernel_launch(void* const* d_in, const int* in_sizes, int n_in,
                              void* d_out, int out_size)
{
    const float* weight = (const float*)d_in[0];
    (void)in_sizes; (void)n_in; (void)out_size;
    pe_interp_flat_kernel<<<NTHREADS / 256, 256>>>(weight, (float*)d_out);
}